// round 1
// baseline (speedup 1.0000x reference)
#include <cuda_runtime.h>
#include <math.h>

#define BB   2
#define SEQ  2048
#define DIM  1024
#define NH   16
#define HD   64
#define MT   (BB*SEQ)   // 4096

// Scratch (allocation-free rule: __device__ globals)
__device__ float g_q[BB*NH*SEQ*HD];
__device__ float g_k[BB*NH*SEQ*HD];
__device__ float g_v[BB*NH*SEQ*HD];
__device__ float g_ctx[MT*DIM];

// ---------------------------------------------------------------------------
// GEMM: C[M,N] = A[M,K] @ W[N,K]^T + bias[N]
// 64x64 tile, 256 threads, 4x4 per thread, BK=16, K-transposed smem tiles.
// SCATTER=true writes into [B,H,S,HD] head-major layout (tile N == head).
// ---------------------------------------------------------------------------
template<bool SCATTER>
__global__ __launch_bounds__(256)
void gemm_kernel(const float* __restrict__ A, const float* __restrict__ W,
                 const float* __restrict__ bias, float* __restrict__ C)
{
    __shared__ float As[16][68];   // [k][m], pad 68 keeps float4 reads conflict-free
    __shared__ float Bs[16][68];   // [k][n]
    const int tid = threadIdx.x;
    const int tx = tid & 15, ty = tid >> 4;
    const int m0 = blockIdx.y * 64, n0 = blockIdx.x * 64;
    const int lr = tid >> 2;          // 0..63 : tile row loaded by this thread
    const int lc = (tid & 3) * 4;     // k-offset of its float4

    const float* Ag = A + (size_t)(m0 + lr) * DIM + lc;
    const float* Wg = W + (size_t)(n0 + lr) * DIM + lc;

    float acc[4][4] = {};
    for (int k0 = 0; k0 < DIM; k0 += 16) {
        float4 a4 = *(const float4*)(Ag + k0);
        float4 b4 = *(const float4*)(Wg + k0);
        __syncthreads();
        As[lc+0][lr] = a4.x; As[lc+1][lr] = a4.y; As[lc+2][lr] = a4.z; As[lc+3][lr] = a4.w;
        Bs[lc+0][lr] = b4.x; Bs[lc+1][lr] = b4.y; Bs[lc+2][lr] = b4.z; Bs[lc+3][lr] = b4.w;
        __syncthreads();
#pragma unroll
        for (int kk = 0; kk < 16; kk++) {
            float4 av = *(const float4*)&As[kk][ty*4];
            float4 bv = *(const float4*)&Bs[kk][tx*4];
            float a[4] = {av.x, av.y, av.z, av.w};
            float b[4] = {bv.x, bv.y, bv.z, bv.w};
#pragma unroll
            for (int i = 0; i < 4; i++)
#pragma unroll
                for (int j = 0; j < 4; j++)
                    acc[i][j] += a[i] * b[j];
        }
    }

    float4 bb = *(const float4*)&bias[n0 + tx*4];
#pragma unroll
    for (int i = 0; i < 4; i++) {
        int m = m0 + ty*4 + i;
        float4 o = make_float4(acc[i][0] + bb.x, acc[i][1] + bb.y,
                               acc[i][2] + bb.z, acc[i][3] + bb.w);
        if (SCATTER) {
            // tile column block == one head (BN=64==HD, gridDim.x=16==NH)
            int b_ = m >> 11;             // m / SEQ
            int s_ = m & (SEQ - 1);
            size_t idx = (((size_t)(b_ * NH + blockIdx.x)) * SEQ + s_) * HD + tx*4;
            *(float4*)&C[idx] = o;
        } else {
            *(float4*)&C[(size_t)m * DIM + n0 + tx*4] = o;
        }
    }
}

// ---------------------------------------------------------------------------
// Flash attention, fp32. grid = (S/64, H, B), 256 threads.
// Per CTA: 64 query rows; loop over 32 K/V tiles of 64 rows.
// Smem: Q^T[hd][s], K^T[hd][s] (reused as P[skv][sq], stride 65), V[skv][hd].
// Row softmax reductions via shfl width 16 (one score row = 16 lanes).
// ---------------------------------------------------------------------------
__global__ __launch_bounds__(256)
void attn_kernel(const float* __restrict__ q, const float* __restrict__ k,
                 const float* __restrict__ v, float* __restrict__ ctx)
{
    extern __shared__ float sm[];
    float* Qs = sm;                // [64 hd][68]
    float* Ks = sm + 64*68;        // [64 hd][68]; reused as Ps (stride 65)
    float* Vs = sm + 2*64*68;      // [64 skv][68]

    const int tid = threadIdx.x;
    const int tx = tid & 15, ty = tid >> 4;
    const int b = blockIdx.z, h = blockIdx.y, q0 = blockIdx.x * 64;

    const float* qg = q + (((size_t)(b*NH + h)) * SEQ + q0) * HD;
    const float* kg = k + ((size_t)(b*NH + h)) * SEQ * HD;
    const float* vg = v + ((size_t)(b*NH + h)) * SEQ * HD;

    const int lr  = tid >> 2;          // 0..63 row
    const int hd0 = (tid & 3) * 16;    // hd chunk base

    // stage Q transposed (once)
    {
        const float* src = qg + lr*HD + hd0;
#pragma unroll
        for (int j = 0; j < 4; j++) {
            float4 t = *(const float4*)(src + j*4);
            int c = hd0 + j*4;
            Qs[(c+0)*68 + lr] = t.x; Qs[(c+1)*68 + lr] = t.y;
            Qs[(c+2)*68 + lr] = t.z; Qs[(c+3)*68 + lr] = t.w;
        }
    }

    float m_i[4], l_i[4], O[4][4];
#pragma unroll
    for (int i = 0; i < 4; i++) {
        m_i[i] = -1e30f; l_i[i] = 0.f;
#pragma unroll
        for (int j = 0; j < 4; j++) O[i][j] = 0.f;
    }

    for (int t = 0; t < SEQ/64; t++) {
        const float* ksrc = kg + (size_t)(t*64 + lr)*HD + hd0;
        const float* vsrc = vg + (size_t)(t*64 + lr)*HD + hd0;
        float4 kr[4], vr[4];
#pragma unroll
        for (int j = 0; j < 4; j++) { kr[j] = *(const float4*)(ksrc + j*4);
                                      vr[j] = *(const float4*)(vsrc + j*4); }
        __syncthreads();   // prior tile's smem reads complete
#pragma unroll
        for (int j = 0; j < 4; j++) {
            int c = hd0 + j*4;
            Ks[(c+0)*68 + lr] = kr[j].x; Ks[(c+1)*68 + lr] = kr[j].y;
            Ks[(c+2)*68 + lr] = kr[j].z; Ks[(c+3)*68 + lr] = kr[j].w;
            *(float4*)&Vs[lr*68 + c] = vr[j];
        }
        __syncthreads();

        // S = Q K^T * 1/sqrt(HD)
        float s[4][4] = {};
#pragma unroll 16
        for (int kk = 0; kk < 64; kk++) {
            float4 q4 = *(const float4*)&Qs[kk*68 + ty*4];
            float4 k4 = *(const float4*)&Ks[kk*68 + tx*4];
            float a[4] = {q4.x, q4.y, q4.z, q4.w};
            float c[4] = {k4.x, k4.y, k4.z, k4.w};
#pragma unroll
            for (int i = 0; i < 4; i++)
#pragma unroll
                for (int j = 0; j < 4; j++)
                    s[i][j] += a[i] * c[j];
        }

        // online softmax (s becomes p in place)
#pragma unroll
        for (int i = 0; i < 4; i++) {
            float mx = -1e30f;
#pragma unroll
            for (int j = 0; j < 4; j++) { s[i][j] *= 0.125f; mx = fmaxf(mx, s[i][j]); }
#pragma unroll
            for (int off = 8; off > 0; off >>= 1)
                mx = fmaxf(mx, __shfl_xor_sync(0xffffffffu, mx, off, 16));
            float mn = fmaxf(m_i[i], mx);
            float corr = __expf(m_i[i] - mn);
            float sum = 0.f;
#pragma unroll
            for (int j = 0; j < 4; j++) { s[i][j] = __expf(s[i][j] - mn); sum += s[i][j]; }
#pragma unroll
            for (int off = 8; off > 0; off >>= 1)
                sum += __shfl_xor_sync(0xffffffffu, sum, off, 16);
            l_i[i] = l_i[i]*corr + sum;
            m_i[i] = mn;
#pragma unroll
            for (int j = 0; j < 4; j++) O[i][j] *= corr;
        }

        __syncthreads();   // done reading Ks; reuse buffer for P (stride 65)
#pragma unroll
        for (int i = 0; i < 4; i++)
#pragma unroll
            for (int j = 0; j < 4; j++)
                Ks[(tx*4 + j)*65 + ty*4 + i] = s[i][j];
        __syncthreads();

        // O += P @ V
#pragma unroll 16
        for (int kk = 0; kk < 64; kk++) {
            float pr[4];
#pragma unroll
            for (int i = 0; i < 4; i++) pr[i] = Ks[kk*65 + ty*4 + i];
            float4 v4 = *(const float4*)&Vs[kk*68 + tx*4];
#pragma unroll
            for (int i = 0; i < 4; i++) {
                O[i][0] += pr[i]*v4.x; O[i][1] += pr[i]*v4.y;
                O[i][2] += pr[i]*v4.z; O[i][3] += pr[i]*v4.w;
            }
        }
    }

    // epilogue: ctx[b, s, h*HD + hd]
#pragma unroll
    for (int i = 0; i < 4; i++) {
        float inv = 1.f / l_i[i];
        int s_ = q0 + ty*4 + i;
        float4 o = make_float4(O[i][0]*inv, O[i][1]*inv, O[i][2]*inv, O[i][3]*inv);
        *(float4*)&ctx[((size_t)(b*SEQ + s_)) * DIM + h*HD + tx*4] = o;
    }
}

// ---------------------------------------------------------------------------
extern "C" void kernel_launch(void* const* d_in, const int* in_sizes, int n_in,
                              void* d_out, int out_size)
{
    const float* x  = (const float*)d_in[0];
    const float* wq = (const float*)d_in[1];
    const float* bq = (const float*)d_in[2];
    const float* wk = (const float*)d_in[3];
    const float* bk = (const float*)d_in[4];
    const float* wv = (const float*)d_in[5];
    const float* bv = (const float*)d_in[6];
    const float* wo = (const float*)d_in[7];
    const float* bo = (const float*)d_in[8];

    float *qp, *kp, *vp, *cp;
    cudaGetSymbolAddress((void**)&qp, g_q);
    cudaGetSymbolAddress((void**)&kp, g_k);
    cudaGetSymbolAddress((void**)&vp, g_v);
    cudaGetSymbolAddress((void**)&cp, g_ctx);

    const int attn_smem = 3 * 64 * 68 * (int)sizeof(float);   // 52224 B > 48K
    cudaFuncSetAttribute(attn_kernel,
                         cudaFuncAttributeMaxDynamicSharedMemorySize, attn_smem);

    dim3 gg(DIM/64, MT/64);   // (16, 64)
    gemm_kernel<true ><<<gg, 256>>>(x,  wq, bq, qp);
    gemm_kernel<true ><<<gg, 256>>>(x,  wk, bk, kp);
    gemm_kernel<true ><<<gg, 256>>>(x,  wv, bv, vp);
    attn_kernel<<<dim3(SEQ/64, NH, BB), 256, attn_smem>>>(qp, kp, vp, cp);
    gemm_kernel<false><<<gg, 256>>>(cp, wo, bo, (float*)d_out);
}

// round 3
// speedup vs baseline: 1.1930x; 1.1930x over previous
#include <cuda_runtime.h>
#include <cstdint>
#include <math.h>

#define BB   2
#define SEQ  2048
#define DIM  1024
#define NH   16
#define HD   64
#define MT   (BB*SEQ)   // 4096

// Scratch (allocation-free rule: __device__ globals)
__device__ float g_q[BB*NH*SEQ*HD];
__device__ float g_k[BB*NH*SEQ*HD];
__device__ float g_v[BB*NH*SEQ*HD];
__device__ float g_ctx[MT*DIM];

// ---------------------------------------------------------------------------
// helpers
// ---------------------------------------------------------------------------
__device__ __forceinline__ uint32_t f2tf32(float x) {
    uint32_t r;
    asm("cvt.rna.tf32.f32 %0, %1;" : "=r"(r) : "f"(x));
    return r;
}

// D += A(tf32,m16k8,row) * B(tf32,k8n8,col)
#define MMA_TF32(d, a, b) \
    asm volatile("mma.sync.aligned.m16n8k8.row.col.f32.tf32.tf32.f32 " \
        "{%0,%1,%2,%3}, {%4,%5,%6,%7}, {%8,%9}, {%0,%1,%2,%3};" \
        : "+f"((d)[0]), "+f"((d)[1]), "+f"((d)[2]), "+f"((d)[3]) \
        : "r"((a)[0]), "r"((a)[1]), "r"((a)[2]), "r"((a)[3]), \
          "r"((b)[0]), "r"((b)[1]))

// float index into a [128][32] tile with 4-float-block XOR swizzle
__device__ __forceinline__ int sidx(int row, int c) {
    return (row << 5) + (((((c) >> 2) ^ (row & 7)) << 2) | ((c) & 3));
}

// ===========================================================================
// 3xTF32 GEMM: C[M,N] = A[M,K] @ W[N,K]^T + bias    (fp32-grade accuracy)
// CTA 128x128, BK=32, 8 warps (2m x 4n), warp tile 64x32 (msub4 x nsub4).
// smem: AH | AL | BH | BL, each 128x32 floats (16KB) = 64KB total.
// SCATTER=true writes into [B,H,S,HD] head-major layout.
// ===========================================================================
#define GEMM_SMEM_BYTES (4 * 4096 * 4)

template<bool SCATTER>
__global__ __launch_bounds__(256, 1)
void gemm_mma(const float* __restrict__ A, const float* __restrict__ W,
              const float* __restrict__ bias, float* __restrict__ C)
{
    extern __shared__ uint32_t smem[];
    uint32_t* AH = smem;
    uint32_t* AL = smem + 4096;
    uint32_t* BH = smem + 8192;
    uint32_t* BL = smem + 12288;

    const int tid = threadIdx.x;
    const int wid = tid >> 5, lane = tid & 31;
    const int g = lane >> 2, tig = lane & 3;
    const int wm = wid & 1, wn = wid >> 1;        // 2m x 4n warp grid
    const int m0 = blockIdx.y * 128, n0 = blockIdx.x * 128;

    // per-thread global->smem map: 4 float4 per operand tile
    int rr[4], cb[4];
#pragma unroll
    for (int j = 0; j < 4; j++) { int f = tid + 256*j; rr[j] = f >> 3; cb[j] = f & 7; }

    float acc[4][4][4];
#pragma unroll
    for (int i = 0; i < 4; i++)
#pragma unroll
        for (int j = 0; j < 4; j++)
#pragma unroll
            for (int q = 0; q < 4; q++) acc[i][j][q] = 0.f;

    float4 ar[4], br[4];
    // preload chunk 0
#pragma unroll
    for (int j = 0; j < 4; j++) {
        ar[j] = *(const float4*)(A + (size_t)(m0 + rr[j]) * DIM + cb[j]*4);
        br[j] = *(const float4*)(W + (size_t)(n0 + rr[j]) * DIM + cb[j]*4);
    }
    // split + store chunk 0
#pragma unroll
    for (int j = 0; j < 4; j++) {
        int slot = (rr[j] << 3) + (cb[j] ^ (rr[j] & 7));
        uint4 h; float4 x = ar[j];
        h.x = f2tf32(x.x); h.y = f2tf32(x.y); h.z = f2tf32(x.z); h.w = f2tf32(x.w);
        uint4 l;
        l.x = f2tf32(x.x - __uint_as_float(h.x));
        l.y = f2tf32(x.y - __uint_as_float(h.y));
        l.z = f2tf32(x.z - __uint_as_float(h.z));
        l.w = f2tf32(x.w - __uint_as_float(h.w));
        ((uint4*)AH)[slot] = h; ((uint4*)AL)[slot] = l;
        x = br[j];
        h.x = f2tf32(x.x); h.y = f2tf32(x.y); h.z = f2tf32(x.z); h.w = f2tf32(x.w);
        l.x = f2tf32(x.x - __uint_as_float(h.x));
        l.y = f2tf32(x.y - __uint_as_float(h.y));
        l.z = f2tf32(x.z - __uint_as_float(h.z));
        l.w = f2tf32(x.w - __uint_as_float(h.w));
        ((uint4*)BH)[slot] = h; ((uint4*)BL)[slot] = l;
    }
    __syncthreads();

    for (int c = 0; c < DIM/32; ++c) {
        // prefetch next chunk (overlaps with MMA work)
        if (c < DIM/32 - 1) {
            int k0 = (c + 1) * 32;
#pragma unroll
            for (int j = 0; j < 4; j++) {
                ar[j] = *(const float4*)(A + (size_t)(m0 + rr[j]) * DIM + k0 + cb[j]*4);
                br[j] = *(const float4*)(W + (size_t)(n0 + rr[j]) * DIM + k0 + cb[j]*4);
            }
        }
        // compute on current smem chunk
#pragma unroll
        for (int kk = 0; kk < 4; kk++) {
            const int c0 = kk*8 + tig, c1 = c0 + 4;
            uint32_t ah[4][4], al[4][4];
#pragma unroll
            for (int i = 0; i < 4; i++) {
                int r0 = wm*64 + i*16 + g, r1 = r0 + 8;
                ah[i][0] = AH[sidx(r0, c0)]; ah[i][1] = AH[sidx(r1, c0)];
                ah[i][2] = AH[sidx(r0, c1)]; ah[i][3] = AH[sidx(r1, c1)];
                al[i][0] = AL[sidx(r0, c0)]; al[i][1] = AL[sidx(r1, c0)];
                al[i][2] = AL[sidx(r0, c1)]; al[i][3] = AL[sidx(r1, c1)];
            }
            uint32_t bh[4][2], bl[4][2];
#pragma unroll
            for (int j = 0; j < 4; j++) {
                int n = wn*32 + j*8 + g;
                bh[j][0] = BH[sidx(n, c0)]; bh[j][1] = BH[sidx(n, c1)];
                bl[j][0] = BL[sidx(n, c0)]; bl[j][1] = BL[sidx(n, c1)];
            }
#pragma unroll
            for (int i = 0; i < 4; i++)
#pragma unroll
                for (int j = 0; j < 4; j++) {
                    MMA_TF32(acc[i][j], ah[i], bh[j]);
                    MMA_TF32(acc[i][j], ah[i], bl[j]);
                    MMA_TF32(acc[i][j], al[i], bh[j]);
                }
        }
        __syncthreads();   // all warps done reading before overwrite
        if (c < DIM/32 - 1) {
#pragma unroll
            for (int j = 0; j < 4; j++) {
                int slot = (rr[j] << 3) + (cb[j] ^ (rr[j] & 7));
                uint4 h; float4 x = ar[j];
                h.x = f2tf32(x.x); h.y = f2tf32(x.y); h.z = f2tf32(x.z); h.w = f2tf32(x.w);
                uint4 l;
                l.x = f2tf32(x.x - __uint_as_float(h.x));
                l.y = f2tf32(x.y - __uint_as_float(h.y));
                l.z = f2tf32(x.z - __uint_as_float(h.z));
                l.w = f2tf32(x.w - __uint_as_float(h.w));
                ((uint4*)AH)[slot] = h; ((uint4*)AL)[slot] = l;
                x = br[j];
                h.x = f2tf32(x.x); h.y = f2tf32(x.y); h.z = f2tf32(x.z); h.w = f2tf32(x.w);
                l.x = f2tf32(x.x - __uint_as_float(h.x));
                l.y = f2tf32(x.y - __uint_as_float(h.y));
                l.z = f2tf32(x.z - __uint_as_float(h.z));
                l.w = f2tf32(x.w - __uint_as_float(h.w));
                ((uint4*)BH)[slot] = h; ((uint4*)BL)[slot] = l;
            }
            __syncthreads();
        }
    }

    // epilogue: C frags -> global, bias fused. float2 stores (pairs never
    // cross a 64-col head boundary: 2*tig+1 <= 7 within an 8-col subtile).
#pragma unroll
    for (int i = 0; i < 4; i++) {
        int r = m0 + wm*64 + i*16 + g;
#pragma unroll
        for (int j = 0; j < 4; j++) {
            int n = n0 + wn*32 + j*8 + 2*tig;
            float b0 = __ldg(bias + n), b1 = __ldg(bias + n + 1);
#pragma unroll
            for (int half = 0; half < 2; half++) {
                int m = r + half*8;
                float2 o = make_float2(acc[i][j][half*2] + b0,
                                       acc[i][j][half*2+1] + b1);
                if (SCATTER) {
                    int b_ = m >> 11, s_ = m & (SEQ - 1);
                    int head = n >> 6, hd = n & 63;
                    *(float2*)&C[(((size_t)(b_*NH + head)) * SEQ + s_) * HD + hd] = o;
                } else {
                    *(float2*)&C[(size_t)m * DIM + n] = o;
                }
            }
        }
    }
}

// ===========================================================================
// Flash attention, fp32 (unchanged, proven). grid = (S/64, H, B), 256 thr.
// ===========================================================================
__global__ __launch_bounds__(256)
void attn_kernel(const float* __restrict__ q, const float* __restrict__ k,
                 const float* __restrict__ v, float* __restrict__ ctx)
{
    extern __shared__ float sm[];
    float* Qs = sm;
    float* Ks = sm + 64*68;
    float* Vs = sm + 2*64*68;

    const int tid = threadIdx.x;
    const int tx = tid & 15, ty = tid >> 4;
    const int b = blockIdx.z, h = blockIdx.y, q0 = blockIdx.x * 64;

    const float* qg = q + (((size_t)(b*NH + h)) * SEQ + q0) * HD;
    const float* kg = k + ((size_t)(b*NH + h)) * SEQ * HD;
    const float* vg = v + ((size_t)(b*NH + h)) * SEQ * HD;

    const int lr  = tid >> 2;
    const int hd0 = (tid & 3) * 16;

    {
        const float* src = qg + lr*HD + hd0;
#pragma unroll
        for (int j = 0; j < 4; j++) {
            float4 t = *(const float4*)(src + j*4);
            int c = hd0 + j*4;
            Qs[(c+0)*68 + lr] = t.x; Qs[(c+1)*68 + lr] = t.y;
            Qs[(c+2)*68 + lr] = t.z; Qs[(c+3)*68 + lr] = t.w;
        }
    }

    float m_i[4], l_i[4], O[4][4];
#pragma unroll
    for (int i = 0; i < 4; i++) {
        m_i[i] = -1e30f; l_i[i] = 0.f;
#pragma unroll
        for (int j = 0; j < 4; j++) O[i][j] = 0.f;
    }

    for (int t = 0; t < SEQ/64; t++) {
        const float* ksrc = kg + (size_t)(t*64 + lr)*HD + hd0;
        const float* vsrc = vg + (size_t)(t*64 + lr)*HD + hd0;
        float4 kr[4], vr[4];
#pragma unroll
        for (int j = 0; j < 4; j++) { kr[j] = *(const float4*)(ksrc + j*4);
                                      vr[j] = *(const float4*)(vsrc + j*4); }
        __syncthreads();
#pragma unroll
        for (int j = 0; j < 4; j++) {
            int c = hd0 + j*4;
            Ks[(c+0)*68 + lr] = kr[j].x; Ks[(c+1)*68 + lr] = kr[j].y;
            Ks[(c+2)*68 + lr] = kr[j].z; Ks[(c+3)*68 + lr] = kr[j].w;
            *(float4*)&Vs[lr*68 + c] = vr[j];
        }
        __syncthreads();

        float s[4][4] = {};
#pragma unroll 16
        for (int kk = 0; kk < 64; kk++) {
            float4 q4 = *(const float4*)&Qs[kk*68 + ty*4];
            float4 k4 = *(const float4*)&Ks[kk*68 + tx*4];
            float a[4] = {q4.x, q4.y, q4.z, q4.w};
            float c[4] = {k4.x, k4.y, k4.z, k4.w};
#pragma unroll
            for (int i = 0; i < 4; i++)
#pragma unroll
                for (int j = 0; j < 4; j++)
                    s[i][j] += a[i] * c[j];
        }

#pragma unroll
        for (int i = 0; i < 4; i++) {
            float mx = -1e30f;
#pragma unroll
            for (int j = 0; j < 4; j++) { s[i][j] *= 0.125f; mx = fmaxf(mx, s[i][j]); }
#pragma unroll
            for (int off = 8; off > 0; off >>= 1)
                mx = fmaxf(mx, __shfl_xor_sync(0xffffffffu, mx, off, 16));
            float mn = fmaxf(m_i[i], mx);
            float corr = __expf(m_i[i] - mn);
            float sum = 0.f;
#pragma unroll
            for (int j = 0; j < 4; j++) { s[i][j] = __expf(s[i][j] - mn); sum += s[i][j]; }
#pragma unroll
            for (int off = 8; off > 0; off >>= 1)
                sum += __shfl_xor_sync(0xffffffffu, sum, off, 16);
            l_i[i] = l_i[i]*corr + sum;
            m_i[i] = mn;
#pragma unroll
            for (int j = 0; j < 4; j++) O[i][j] *= corr;
        }

        __syncthreads();
#pragma unroll
        for (int i = 0; i < 4; i++)
#pragma unroll
            for (int j = 0; j < 4; j++)
                Ks[(tx*4 + j)*65 + ty*4 + i] = s[i][j];
        __syncthreads();

#pragma unroll 16
        for (int kk = 0; kk < 64; kk++) {
            float pr[4];
#pragma unroll
            for (int i = 0; i < 4; i++) pr[i] = Ks[kk*65 + ty*4 + i];
            float4 v4 = *(const float4*)&Vs[kk*68 + tx*4];
#pragma unroll
            for (int i = 0; i < 4; i++) {
                O[i][0] += pr[i]*v4.x; O[i][1] += pr[i]*v4.y;
                O[i][2] += pr[i]*v4.z; O[i][3] += pr[i]*v4.w;
            }
        }
    }

#pragma unroll
    for (int i = 0; i < 4; i++) {
        float inv = 1.f / l_i[i];
        int s_ = q0 + ty*4 + i;
        float4 o = make_float4(O[i][0]*inv, O[i][1]*inv, O[i][2]*inv, O[i][3]*inv);
        *(float4*)&ctx[((size_t)(b*SEQ + s_)) * DIM + h*HD + tx*4] = o;
    }
}

// ===========================================================================
extern "C" void kernel_launch(void* const* d_in, const int* in_sizes, int n_in,
                              void* d_out, int out_size)
{
    const float* x  = (const float*)d_in[0];
    const float* wq = (const float*)d_in[1];
    const float* bq = (const float*)d_in[2];
    const float* wk = (const float*)d_in[3];
    const float* bk = (const float*)d_in[4];
    const float* wv = (const float*)d_in[5];
    const float* bv = (const float*)d_in[6];
    const float* wo = (const float*)d_in[7];
    const float* bo = (const float*)d_in[8];

    float *qp, *kp, *vp, *cp;
    cudaGetSymbolAddress((void**)&qp, g_q);
    cudaGetSymbolAddress((void**)&kp, g_k);
    cudaGetSymbolAddress((void**)&vp, g_v);
    cudaGetSymbolAddress((void**)&cp, g_ctx);

    const int attn_smem = 3 * 64 * 68 * (int)sizeof(float);
    cudaFuncSetAttribute(attn_kernel,
                         cudaFuncAttributeMaxDynamicSharedMemorySize, attn_smem);
    cudaFuncSetAttribute(gemm_mma<true>,
                         cudaFuncAttributeMaxDynamicSharedMemorySize, GEMM_SMEM_BYTES);
    cudaFuncSetAttribute(gemm_mma<false>,
                         cudaFuncAttributeMaxDynamicSharedMemorySize, GEMM_SMEM_BYTES);

    dim3 gg(DIM/128, MT/128);   // (8, 32)
    gemm_mma<true ><<<gg, 256, GEMM_SMEM_BYTES>>>(x,  wq, bq, qp);
    gemm_mma<true ><<<gg, 256, GEMM_SMEM_BYTES>>>(x,  wk, bk, kp);
    gemm_mma<true ><<<gg, 256, GEMM_SMEM_BYTES>>>(x,  wv, bv, vp);
    attn_kernel<<<dim3(SEQ/64, NH, BB), 256, attn_smem>>>(qp, kp, vp, cp);
    gemm_mma<false><<<gg, 256, GEMM_SMEM_BYTES>>>(cp, wo, bo, (float*)d_out);
}

// round 4
// speedup vs baseline: 2.1613x; 1.8116x over previous
#include <cuda_runtime.h>
#include <cstdint>
#include <math.h>

#define BB   2
#define SEQ  2048
#define DIM  1024
#define NH   16
#define HD   64
#define MT   (BB*SEQ)   // 4096

// Scratch (allocation-free rule: __device__ globals)
__device__ float g_q[BB*NH*SEQ*HD];
__device__ float g_k[BB*NH*SEQ*HD];
__device__ float g_v[BB*NH*SEQ*HD];
__device__ float g_ctx[MT*DIM];

// ---------------------------------------------------------------------------
// helpers
// ---------------------------------------------------------------------------
__device__ __forceinline__ uint32_t f2tf32(float x) {
    uint32_t r;
    asm("cvt.rna.tf32.f32 %0, %1;" : "=r"(r) : "f"(x));
    return r;
}
__device__ __forceinline__ uint32_t smem_u32(const void* p) {
    uint32_t a;
    asm("{ .reg .u64 t; cvta.to.shared.u64 t, %1; cvt.u32.u64 %0, t; }"
        : "=r"(a) : "l"(p));
    return a;
}
__device__ __forceinline__ void cp16(uint32_t dst, const void* src) {
    asm volatile("cp.async.ca.shared.global [%0], [%1], 16;" :: "r"(dst), "l"(src));
}
#define CP_COMMIT() asm volatile("cp.async.commit_group;" ::: "memory")
#define CP_WAIT0()  asm volatile("cp.async.wait_group 0;" ::: "memory")

// D += A(tf32,m16k8,row) * B(tf32,k8n8,col)
#define MMA_TF32(d, a, b) \
    asm volatile("mma.sync.aligned.m16n8k8.row.col.f32.tf32.tf32.f32 " \
        "{%0,%1,%2,%3}, {%4,%5,%6,%7}, {%8,%9}, {%0,%1,%2,%3};" \
        : "+f"((d)[0]), "+f"((d)[1]), "+f"((d)[2]), "+f"((d)[3]) \
        : "r"((a)[0]), "r"((a)[1]), "r"((a)[2]), "r"((a)[3]), \
          "r"((b)[0]), "r"((b)[1]))

// float index into a [128][32] tile with 4-float-block XOR swizzle
__device__ __forceinline__ int sidx(int row, int c) {
    return (row << 5) + (((((c) >> 2) ^ (row & 7)) << 2) | ((c) & 3));
}

// ===========================================================================
// 3xTF32 GEMM: C[M,N] = A[M,K] @ W[N,K]^T + bias  (unchanged core from R3)
// SCATTER=true additionally rounds outputs to tf32 (rna) so the attention
// MMA's operand truncation is exact.
// ===========================================================================
#define GEMM_SMEM_BYTES (4 * 4096 * 4)

template<bool SCATTER>
__global__ __launch_bounds__(256, 1)
void gemm_mma(const float* __restrict__ A, const float* __restrict__ W,
              const float* __restrict__ bias, float* __restrict__ C)
{
    extern __shared__ uint32_t smem[];
    uint32_t* AH = smem;
    uint32_t* AL = smem + 4096;
    uint32_t* BH = smem + 8192;
    uint32_t* BL = smem + 12288;

    const int tid = threadIdx.x;
    const int wid = tid >> 5, lane = tid & 31;
    const int g = lane >> 2, tig = lane & 3;
    const int wm = wid & 1, wn = wid >> 1;
    const int m0 = blockIdx.y * 128, n0 = blockIdx.x * 128;

    int rr[4], cb[4];
#pragma unroll
    for (int j = 0; j < 4; j++) { int f = tid + 256*j; rr[j] = f >> 3; cb[j] = f & 7; }

    float acc[4][4][4];
#pragma unroll
    for (int i = 0; i < 4; i++)
#pragma unroll
        for (int j = 0; j < 4; j++)
#pragma unroll
            for (int q = 0; q < 4; q++) acc[i][j][q] = 0.f;

    float4 ar[4], br[4];
#pragma unroll
    for (int j = 0; j < 4; j++) {
        ar[j] = *(const float4*)(A + (size_t)(m0 + rr[j]) * DIM + cb[j]*4);
        br[j] = *(const float4*)(W + (size_t)(n0 + rr[j]) * DIM + cb[j]*4);
    }
#pragma unroll
    for (int j = 0; j < 4; j++) {
        int slot = (rr[j] << 3) + (cb[j] ^ (rr[j] & 7));
        uint4 h; float4 x = ar[j];
        h.x = f2tf32(x.x); h.y = f2tf32(x.y); h.z = f2tf32(x.z); h.w = f2tf32(x.w);
        uint4 l;
        l.x = f2tf32(x.x - __uint_as_float(h.x));
        l.y = f2tf32(x.y - __uint_as_float(h.y));
        l.z = f2tf32(x.z - __uint_as_float(h.z));
        l.w = f2tf32(x.w - __uint_as_float(h.w));
        ((uint4*)AH)[slot] = h; ((uint4*)AL)[slot] = l;
        x = br[j];
        h.x = f2tf32(x.x); h.y = f2tf32(x.y); h.z = f2tf32(x.z); h.w = f2tf32(x.w);
        l.x = f2tf32(x.x - __uint_as_float(h.x));
        l.y = f2tf32(x.y - __uint_as_float(h.y));
        l.z = f2tf32(x.z - __uint_as_float(h.z));
        l.w = f2tf32(x.w - __uint_as_float(h.w));
        ((uint4*)BH)[slot] = h; ((uint4*)BL)[slot] = l;
    }
    __syncthreads();

    for (int c = 0; c < DIM/32; ++c) {
        if (c < DIM/32 - 1) {
            int k0 = (c + 1) * 32;
#pragma unroll
            for (int j = 0; j < 4; j++) {
                ar[j] = *(const float4*)(A + (size_t)(m0 + rr[j]) * DIM + k0 + cb[j]*4);
                br[j] = *(const float4*)(W + (size_t)(n0 + rr[j]) * DIM + k0 + cb[j]*4);
            }
        }
#pragma unroll
        for (int kk = 0; kk < 4; kk++) {
            const int c0 = kk*8 + tig, c1 = c0 + 4;
            uint32_t ah[4][4], al[4][4];
#pragma unroll
            for (int i = 0; i < 4; i++) {
                int r0 = wm*64 + i*16 + g, r1 = r0 + 8;
                ah[i][0] = AH[sidx(r0, c0)]; ah[i][1] = AH[sidx(r1, c0)];
                ah[i][2] = AH[sidx(r0, c1)]; ah[i][3] = AH[sidx(r1, c1)];
                al[i][0] = AL[sidx(r0, c0)]; al[i][1] = AL[sidx(r1, c0)];
                al[i][2] = AL[sidx(r0, c1)]; al[i][3] = AL[sidx(r1, c1)];
            }
            uint32_t bh[4][2], bl[4][2];
#pragma unroll
            for (int j = 0; j < 4; j++) {
                int n = wn*32 + j*8 + g;
                bh[j][0] = BH[sidx(n, c0)]; bh[j][1] = BH[sidx(n, c1)];
                bl[j][0] = BL[sidx(n, c0)]; bl[j][1] = BL[sidx(n, c1)];
            }
#pragma unroll
            for (int i = 0; i < 4; i++)
#pragma unroll
                for (int j = 0; j < 4; j++) {
                    MMA_TF32(acc[i][j], ah[i], bh[j]);
                    MMA_TF32(acc[i][j], ah[i], bl[j]);
                    MMA_TF32(acc[i][j], al[i], bh[j]);
                }
        }
        __syncthreads();
        if (c < DIM/32 - 1) {
#pragma unroll
            for (int j = 0; j < 4; j++) {
                int slot = (rr[j] << 3) + (cb[j] ^ (rr[j] & 7));
                uint4 h; float4 x = ar[j];
                h.x = f2tf32(x.x); h.y = f2tf32(x.y); h.z = f2tf32(x.z); h.w = f2tf32(x.w);
                uint4 l;
                l.x = f2tf32(x.x - __uint_as_float(h.x));
                l.y = f2tf32(x.y - __uint_as_float(h.y));
                l.z = f2tf32(x.z - __uint_as_float(h.z));
                l.w = f2tf32(x.w - __uint_as_float(h.w));
                ((uint4*)AH)[slot] = h; ((uint4*)AL)[slot] = l;
                x = br[j];
                h.x = f2tf32(x.x); h.y = f2tf32(x.y); h.z = f2tf32(x.z); h.w = f2tf32(x.w);
                l.x = f2tf32(x.x - __uint_as_float(h.x));
                l.y = f2tf32(x.y - __uint_as_float(h.y));
                l.z = f2tf32(x.z - __uint_as_float(h.z));
                l.w = f2tf32(x.w - __uint_as_float(h.w));
                ((uint4*)BH)[slot] = h; ((uint4*)BL)[slot] = l;
            }
            __syncthreads();
        }
    }

#pragma unroll
    for (int i = 0; i < 4; i++) {
        int r = m0 + wm*64 + i*16 + g;
#pragma unroll
        for (int j = 0; j < 4; j++) {
            int n = n0 + wn*32 + j*8 + 2*tig;
            float b0 = __ldg(bias + n), b1 = __ldg(bias + n + 1);
#pragma unroll
            for (int half = 0; half < 2; half++) {
                int m = r + half*8;
                float v0 = acc[i][j][half*2] + b0;
                float v1 = acc[i][j][half*2+1] + b1;
                if (SCATTER) {
                    // round q/k/v to tf32 so attention MMA truncation is exact
                    float2 o = make_float2(__uint_as_float(f2tf32(v0)),
                                           __uint_as_float(f2tf32(v1)));
                    int b_ = m >> 11, s_ = m & (SEQ - 1);
                    int head = n >> 6, hd = n & 63;
                    *(float2*)&C[(((size_t)(b_*NH + head)) * SEQ + s_) * HD + hd] = o;
                } else {
                    float2 o = make_float2(v0, v1);
                    *(float2*)&C[(size_t)m * DIM + n] = o;
                }
            }
        }
    }
}

// ===========================================================================
// Tensor-core flash attention (tf32 mma.sync).
// grid = (S/64, H, B), 128 threads (4 warps = 4 m16 strips of the 64 q rows).
// KV tiles of 64, cp.async double-buffered. K smem stride 68, V stride 72,
// P stride 68 (conflict-free fragment LDS patterns).
// q/k/v inputs are pre-rounded to tf32 by the projection epilogue.
// ===========================================================================
#define ATTN_STAGE_F  (68*64 + 72*64)          // 8960 floats per stage
#define ATTN_SMEM     ((2*ATTN_STAGE_F + 68*64) * 4)   // 89088 bytes

__global__ __launch_bounds__(128, 2)
void attn_mma(const float* __restrict__ q, const float* __restrict__ k,
              const float* __restrict__ v, float* __restrict__ ctx)
{
    extern __shared__ float sm[];
    const uint32_t sb = smem_u32(sm);
    const int tid = threadIdx.x;
    const int lane = tid & 31, wm = tid >> 5;
    const int g = lane >> 2, tig = lane & 3;
    const int b = blockIdx.z, h = blockIdx.y, q0 = blockIdx.x * 64;

    const float* qg = q + (((size_t)(b*NH + h)) * SEQ + q0) * HD;
    const float* kg = k + ((size_t)(b*NH + h)) * SEQ * HD;
    const float* vg = v + ((size_t)(b*NH + h)) * SEQ * HD;

    float* Pbuf = sm + 2*ATTN_STAGE_F;

    // ---- stage Q (x 1/8, exact in tf32) then capture A-fragments ----
#pragma unroll
    for (int j = 0; j < 8; j++) {
        int id = tid + 128*j;                 // 0..1023
        int r = id >> 4, c = (id & 15) * 4;
        float4 t = *(const float4*)(qg + r*HD + c);
        t.x *= 0.125f; t.y *= 0.125f; t.z *= 0.125f; t.w *= 0.125f;
        *(float4*)&Pbuf[r*68 + c] = t;
    }
    __syncthreads();
    uint32_t qf[8][4];
    {
        int r0 = wm*16 + g;
#pragma unroll
        for (int kc = 0; kc < 8; kc++) {
            qf[kc][0] = __float_as_uint(Pbuf[ r0      *68 + kc*8 + tig    ]);
            qf[kc][1] = __float_as_uint(Pbuf[(r0 + 8) *68 + kc*8 + tig    ]);
            qf[kc][2] = __float_as_uint(Pbuf[ r0      *68 + kc*8 + tig + 4]);
            qf[kc][3] = __float_as_uint(Pbuf[(r0 + 8) *68 + kc*8 + tig + 4]);
        }
    }
    // (warp reads only its own rows; P rewrites of those rows happen after
    //  the tile-0 __syncthreads below, in the same warp's program order)

    // ---- preload KV tile 0 ----
#pragma unroll
    for (int j = 0; j < 8; j++) {
        int id = tid + 128*j;
        int r = id >> 4, c = (id & 15) * 4;
        cp16(sb + (r*68 + c)*4,        kg + r*HD + c);
        cp16(sb + (4352 + r*72 + c)*4, vg + r*HD + c);
    }
    CP_COMMIT();

    float o[8][4];
#pragma unroll
    for (int nc = 0; nc < 8; nc++)
#pragma unroll
        for (int e = 0; e < 4; e++) o[nc][e] = 0.f;
    float m0 = -1e30f, m1 = -1e30f, l0 = 0.f, l1 = 0.f;
    const int r0 = wm*16 + g;

    for (int t = 0; t < SEQ/64; ++t) {
        CP_WAIT0();
        __syncthreads();
        if (t < SEQ/64 - 1) {
            int st = ((t+1) & 1) * ATTN_STAGE_F;
            const float* kn = kg + (size_t)(t+1)*64*HD;
            const float* vn = vg + (size_t)(t+1)*64*HD;
#pragma unroll
            for (int j = 0; j < 8; j++) {
                int id = tid + 128*j;
                int r = id >> 4, c = (id & 15) * 4;
                cp16(sb + (st + r*68 + c)*4,        kn + r*HD + c);
                cp16(sb + (st + 4352 + r*72 + c)*4, vn + r*HD + c);
            }
            CP_COMMIT();
        }
        const float* Ks = sm + (t & 1) * ATTN_STAGE_F;
        const float* Vs = Ks + 4352;

        // ---- S = (Q/8) K^T ----
        float s[8][4];
#pragma unroll
        for (int nc = 0; nc < 8; nc++) {
#pragma unroll
            for (int e = 0; e < 4; e++) s[nc][e] = 0.f;
#pragma unroll
            for (int kc = 0; kc < 8; kc++) {
                uint32_t bfr[2];
                bfr[0] = __float_as_uint(Ks[(nc*8 + g)*68 + kc*8 + tig    ]);
                bfr[1] = __float_as_uint(Ks[(nc*8 + g)*68 + kc*8 + tig + 4]);
                MMA_TF32(s[nc], qf[kc], bfr);
            }
        }

        // ---- online softmax on fragments (rows r0, r0+8) ----
        float mx0 = -1e30f, mx1 = -1e30f;
#pragma unroll
        for (int nc = 0; nc < 8; nc++) {
            mx0 = fmaxf(mx0, fmaxf(s[nc][0], s[nc][1]));
            mx1 = fmaxf(mx1, fmaxf(s[nc][2], s[nc][3]));
        }
        mx0 = fmaxf(mx0, __shfl_xor_sync(0xffffffffu, mx0, 1));
        mx0 = fmaxf(mx0, __shfl_xor_sync(0xffffffffu, mx0, 2));
        mx1 = fmaxf(mx1, __shfl_xor_sync(0xffffffffu, mx1, 1));
        mx1 = fmaxf(mx1, __shfl_xor_sync(0xffffffffu, mx1, 2));
        float mn0 = fmaxf(m0, mx0), mn1 = fmaxf(m1, mx1);
        float c0 = __expf(m0 - mn0), c1 = __expf(m1 - mn1);
        float sum0 = 0.f, sum1 = 0.f;
#pragma unroll
        for (int nc = 0; nc < 8; nc++) {
            s[nc][0] = __expf(s[nc][0] - mn0); sum0 += s[nc][0];
            s[nc][1] = __expf(s[nc][1] - mn0); sum0 += s[nc][1];
            s[nc][2] = __expf(s[nc][2] - mn1); sum1 += s[nc][2];
            s[nc][3] = __expf(s[nc][3] - mn1); sum1 += s[nc][3];
        }
        sum0 += __shfl_xor_sync(0xffffffffu, sum0, 1);
        sum0 += __shfl_xor_sync(0xffffffffu, sum0, 2);
        sum1 += __shfl_xor_sync(0xffffffffu, sum1, 1);
        sum1 += __shfl_xor_sync(0xffffffffu, sum1, 2);
        l0 = l0*c0 + sum0;  l1 = l1*c1 + sum1;
        m0 = mn0;           m1 = mn1;
#pragma unroll
        for (int nc = 0; nc < 8; nc++) {
            o[nc][0] *= c0; o[nc][1] *= c0;
            o[nc][2] *= c1; o[nc][3] *= c1;
        }

        // ---- P (tf32-rounded) -> smem, own rows only ----
#pragma unroll
        for (int nc = 0; nc < 8; nc++) {
            *(float2*)&Pbuf[ r0    *68 + nc*8 + 2*tig] =
                make_float2(__uint_as_float(f2tf32(s[nc][0])),
                            __uint_as_float(f2tf32(s[nc][1])));
            *(float2*)&Pbuf[(r0+8) *68 + nc*8 + 2*tig] =
                make_float2(__uint_as_float(f2tf32(s[nc][2])),
                            __uint_as_float(f2tf32(s[nc][3])));
        }
        __syncwarp();

        // ---- O += P V ----
#pragma unroll
        for (int kc = 0; kc < 8; kc++) {
            uint32_t a[4];
            a[0] = __float_as_uint(Pbuf[ r0    *68 + kc*8 + tig    ]);
            a[1] = __float_as_uint(Pbuf[(r0+8) *68 + kc*8 + tig    ]);
            a[2] = __float_as_uint(Pbuf[ r0    *68 + kc*8 + tig + 4]);
            a[3] = __float_as_uint(Pbuf[(r0+8) *68 + kc*8 + tig + 4]);
#pragma unroll
            for (int nc = 0; nc < 8; nc++) {
                uint32_t bfr[2];
                bfr[0] = __float_as_uint(Vs[(kc*8 + tig    )*72 + nc*8 + g]);
                bfr[1] = __float_as_uint(Vs[(kc*8 + tig + 4)*72 + nc*8 + g]);
                MMA_TF32(o[nc], a, bfr);
            }
        }
        __syncwarp();   // P reads done before next tile's rewrite
    }

    // ---- epilogue: ctx[b, q0+row, h*64 + hd] ----
    float inv0 = 1.f / l0, inv1 = 1.f / l1;
    size_t base0 = ((size_t)(b*SEQ + q0 + r0    )) * DIM + h*HD;
    size_t base1 = ((size_t)(b*SEQ + q0 + r0 + 8)) * DIM + h*HD;
#pragma unroll
    for (int nc = 0; nc < 8; nc++) {
        *(float2*)&ctx[base0 + nc*8 + 2*tig] =
            make_float2(o[nc][0]*inv0, o[nc][1]*inv0);
        *(float2*)&ctx[base1 + nc*8 + 2*tig] =
            make_float2(o[nc][2]*inv1, o[nc][3]*inv1);
    }
}

// ===========================================================================
extern "C" void kernel_launch(void* const* d_in, const int* in_sizes, int n_in,
                              void* d_out, int out_size)
{
    const float* x  = (const float*)d_in[0];
    const float* wq = (const float*)d_in[1];
    const float* bq = (const float*)d_in[2];
    const float* wk = (const float*)d_in[3];
    const float* bk = (const float*)d_in[4];
    const float* wv = (const float*)d_in[5];
    const float* bv = (const float*)d_in[6];
    const float* wo = (const float*)d_in[7];
    const float* bo = (const float*)d_in[8];

    float *qp, *kp, *vp, *cp;
    cudaGetSymbolAddress((void**)&qp, g_q);
    cudaGetSymbolAddress((void**)&kp, g_k);
    cudaGetSymbolAddress((void**)&vp, g_v);
    cudaGetSymbolAddress((void**)&cp, g_ctx);

    cudaFuncSetAttribute(attn_mma,
                         cudaFuncAttributeMaxDynamicSharedMemorySize, ATTN_SMEM);
    cudaFuncSetAttribute(gemm_mma<true>,
                         cudaFuncAttributeMaxDynamicSharedMemorySize, GEMM_SMEM_BYTES);
    cudaFuncSetAttribute(gemm_mma<false>,
                         cudaFuncAttributeMaxDynamicSharedMemorySize, GEMM_SMEM_BYTES);

    dim3 gg(DIM/128, MT/128);   // (8, 32)
    gemm_mma<true ><<<gg, 256, GEMM_SMEM_BYTES>>>(x,  wq, bq, qp);
    gemm_mma<true ><<<gg, 256, GEMM_SMEM_BYTES>>>(x,  wk, bk, kp);
    gemm_mma<true ><<<gg, 256, GEMM_SMEM_BYTES>>>(x,  wv, bv, vp);
    attn_mma<<<dim3(SEQ/64, NH, BB), 128, ATTN_SMEM>>>(qp, kp, vp, cp);
    gemm_mma<false><<<gg, 256, GEMM_SMEM_BYTES>>>(cp, wo, bo, (float*)d_out);
}

// round 5
// speedup vs baseline: 2.6709x; 1.2358x over previous
#include <cuda_runtime.h>
#include <cstdint>
#include <math.h>

#define BB   2
#define SEQ  2048
#define DIM  1024
#define NH   16
#define HD   64
#define MT   (BB*SEQ)   // 4096

// Scratch (allocation-free rule: __device__ globals)
__device__ float g_q[BB*NH*SEQ*HD];
__device__ float g_k[BB*NH*SEQ*HD];
__device__ float g_v[BB*NH*SEQ*HD];
__device__ float g_ctx[MT*DIM];

// ---------------------------------------------------------------------------
// helpers
// ---------------------------------------------------------------------------
__device__ __forceinline__ uint32_t f2tf32(float x) {
    uint32_t r;
    asm("cvt.rna.tf32.f32 %0, %1;" : "=r"(r) : "f"(x));
    return r;
}
__device__ __forceinline__ uint32_t smem_u32(const void* p) {
    uint32_t a;
    asm("{ .reg .u64 t; cvta.to.shared.u64 t, %1; cvt.u32.u64 %0, t; }"
        : "=r"(a) : "l"(p));
    return a;
}
__device__ __forceinline__ void cp16(uint32_t dst, const void* src) {
    asm volatile("cp.async.ca.shared.global [%0], [%1], 16;" :: "r"(dst), "l"(src));
}
#define CP_COMMIT() asm volatile("cp.async.commit_group;" ::: "memory")
#define CP_WAIT0()  asm volatile("cp.async.wait_group 0;" ::: "memory")

// D += A(tf32,m16k8,row) * B(tf32,k8n8,col)
#define MMA_TF32(d, a, b) \
    asm volatile("mma.sync.aligned.m16n8k8.row.col.f32.tf32.tf32.f32 " \
        "{%0,%1,%2,%3}, {%4,%5,%6,%7}, {%8,%9}, {%0,%1,%2,%3};" \
        : "+f"((d)[0]), "+f"((d)[1]), "+f"((d)[2]), "+f"((d)[3]) \
        : "r"((a)[0]), "r"((a)[1]), "r"((a)[2]), "r"((a)[3]), \
          "r"((b)[0]), "r"((b)[1]))

// D += A(bf16,m16k16,row) * B(bf16,k16n8,col)
#define MMA_BF16(d, a0, a1, a2, a3, b0, b1) \
    asm volatile("mma.sync.aligned.m16n8k16.row.col.f32.bf16.bf16.f32 " \
        "{%0,%1,%2,%3}, {%4,%5,%6,%7}, {%8,%9}, {%0,%1,%2,%3};" \
        : "+f"((d)[0]), "+f"((d)[1]), "+f"((d)[2]), "+f"((d)[3]) \
        : "r"(a0), "r"(a1), "r"(a2), "r"(a3), "r"(b0), "r"(b1))

#define LDSM4(d0, d1, d2, d3, a) \
    asm volatile("ldmatrix.sync.aligned.m8n8.x4.shared.b16 {%0,%1,%2,%3}, [%4];" \
        : "=r"(d0), "=r"(d1), "=r"(d2), "=r"(d3) : "r"(a))

// pack: word = { low = bf16(lo_elem), high = bf16(hi_elem) }
__device__ __forceinline__ uint32_t packbf(float lo_elem, float hi_elem) {
    uint32_t r;
    asm("cvt.rn.bf16x2.f32 %0, %1, %2;" : "=r"(r) : "f"(hi_elem), "f"(lo_elem));
    return r;
}
__device__ __forceinline__ float ubf_lo(uint32_t w) { return __uint_as_float(w << 16); }
__device__ __forceinline__ float ubf_hi(uint32_t w) { return __uint_as_float(w & 0xFFFF0000u); }

// convert float4 -> 2 hi words + 2 lo words (bf16x2, memory order)
__device__ __forceinline__ void split4(float4 x, uint32_t* h, uint32_t* l) {
    h[0] = packbf(x.x, x.y);
    h[1] = packbf(x.z, x.w);
    l[0] = packbf(x.x - ubf_lo(h[0]), x.y - ubf_hi(h[0]));
    l[1] = packbf(x.z - ubf_lo(h[1]), x.w - ubf_hi(h[1]));
}

// ===========================================================================
// 3xBF16 GEMM: C[M,N] = A[M,K] @ W[N,K]^T + bias   (fp32-grade accuracy)
// CTA 128x128, BK=32, 8 warps (2m x 4n), warp tile 64x32.
// Double-buffered smem: per stage AHi|ALo|BHi|BLo, each [128 rows x 32 bf16]
// in a line-interleaved swizzle (2 rows / 128B line, 16B chunks XOR line&7).
// grid.z selects W/bias/C (QKV fused). SCATTER writes [B,H,S,HD] + tf32 round.
// ===========================================================================
#define GSTAGE 32768
#define GEMM_SMEM_BYTES (2*GSTAGE)   // 64 KB

template<bool SCATTER>
__global__ __launch_bounds__(256, 1)
void gemm_bf16(const float* __restrict__ A,
               const float* __restrict__ w0, const float* __restrict__ w1,
               const float* __restrict__ w2,
               const float* __restrict__ bb0, const float* __restrict__ bb1,
               const float* __restrict__ bb2,
               float* __restrict__ c0, float* __restrict__ c1, float* __restrict__ c2)
{
    extern __shared__ char smem[];
    const uint32_t sb = smem_u32(smem);
    const int z = blockIdx.z;
    const float* W    = (z == 0) ? w0 : (z == 1) ? w1 : w2;
    const float* bias = (z == 0) ? bb0 : (z == 1) ? bb1 : bb2;
    float* C          = (z == 0) ? c0 : (z == 1) ? c1 : c2;

    const int tid = threadIdx.x;
    const int wid = tid >> 5, lane = tid & 31;
    const int g = lane >> 2, tig = lane & 3;
    const int wm = wid & 1, wn = wid >> 1;           // 2m x 4n warp grid
    const int m0 = blockIdx.y * 128, n0 = blockIdx.x * 128;

    // ---- loader map: thread -> (row, k-half of 16) ----
    const int lr = tid >> 1, lh = tid & 1;
    const float* Ag = A + (size_t)(m0 + lr) * DIM + lh*16;
    const float* Wg = W + (size_t)(n0 + lr) * DIM + lh*16;
    // store byte offsets (2 chunks per buffer): line*128 + pch*16
    uint32_t soff[2];
#pragma unroll
    for (int j = 0; j < 2; j++)
        soff[j] = (uint32_t)((lr >> 1)*128 + ((((lr & 1)*4 + 2*lh + j) ^ ((lr >> 1) & 7)) * 16));

    // ---- ldmatrix per-lane offsets (independent of subtile), kk = 0,1 ----
    const int rl  = ((lane >> 3) & 1) * 8 + (lane & 7);
    const int chl = lane >> 4;
    uint32_t aoff[2];
#pragma unroll
    for (int kk = 0; kk < 2; kk++)
        aoff[kk] = (uint32_t)((rl >> 1)*128 + ((((rl & 1)*4 + 2*kk + chl) ^ (rl >> 1)) * 16));

    float acc[4][4][4];
#pragma unroll
    for (int i = 0; i < 4; i++)
#pragma unroll
        for (int j = 0; j < 4; j++)
#pragma unroll
            for (int q = 0; q < 4; q++) acc[i][j][q] = 0.f;

    float4 ar[4], br[4];
    // ---- prologue: chunk 0 ----
#pragma unroll
    for (int j = 0; j < 4; j++) {
        ar[j] = *(const float4*)(Ag + j*4);
        br[j] = *(const float4*)(Wg + j*4);
    }
    {
        char* st = smem;
        uint32_t h[2][2], l[2][2];
        split4(ar[0], h[0], l[0]); split4(ar[1], h[1], l[1]);
        *(uint4*)(st +         soff[0]) = make_uint4(h[0][0], h[0][1], h[1][0], h[1][1]);
        *(uint4*)(st +  8192 + soff[0]) = make_uint4(l[0][0], l[0][1], l[1][0], l[1][1]);
        split4(ar[2], h[0], l[0]); split4(ar[3], h[1], l[1]);
        *(uint4*)(st +         soff[1]) = make_uint4(h[0][0], h[0][1], h[1][0], h[1][1]);
        *(uint4*)(st +  8192 + soff[1]) = make_uint4(l[0][0], l[0][1], l[1][0], l[1][1]);
        split4(br[0], h[0], l[0]); split4(br[1], h[1], l[1]);
        *(uint4*)(st + 16384 + soff[0]) = make_uint4(h[0][0], h[0][1], h[1][0], h[1][1]);
        *(uint4*)(st + 24576 + soff[0]) = make_uint4(l[0][0], l[0][1], l[1][0], l[1][1]);
        split4(br[2], h[0], l[0]); split4(br[3], h[1], l[1]);
        *(uint4*)(st + 16384 + soff[1]) = make_uint4(h[0][0], h[0][1], h[1][0], h[1][1]);
        *(uint4*)(st + 24576 + soff[1]) = make_uint4(l[0][0], l[0][1], l[1][0], l[1][1]);
    }
    __syncthreads();

    for (int c = 0; c < DIM/32; ++c) {
        const uint32_t stage = sb + (uint32_t)(c & 1) * GSTAGE;
        // prefetch next chunk into registers
        if (c < DIM/32 - 1) {
            int k0 = (c + 1) * 32;
#pragma unroll
            for (int j = 0; j < 4; j++) {
                ar[j] = *(const float4*)(Ag + k0 + j*4);
                br[j] = *(const float4*)(Wg + k0 + j*4);
            }
        }
        // ---- compute on current stage ----
#pragma unroll
        for (int kk = 0; kk < 2; kk++) {
            uint32_t ah[4][4], al[4][4];
#pragma unroll
            for (int i = 0; i < 4; i++) {
                uint32_t base = stage + (uint32_t)(wm*4096 + i*1024) + aoff[kk];
                LDSM4(ah[i][0], ah[i][1], ah[i][2], ah[i][3], base);
                LDSM4(al[i][0], al[i][1], al[i][2], al[i][3], base + 8192);
            }
            uint32_t bh[4][2], bl[4][2];
#pragma unroll
            for (int nn = 0; nn < 2; nn++) {
                uint32_t base = stage + 16384u + (uint32_t)(wn*2048 + nn*1024) + aoff[kk];
                uint32_t q0, q1, q2, q3;
                LDSM4(q0, q1, q2, q3, base);
                bh[nn*2][0] = q0; bh[nn*2][1] = q2;
                bh[nn*2+1][0] = q1; bh[nn*2+1][1] = q3;
                LDSM4(q0, q1, q2, q3, base + 8192);
                bl[nn*2][0] = q0; bl[nn*2][1] = q2;
                bl[nn*2+1][0] = q1; bl[nn*2+1][1] = q3;
            }
#pragma unroll
            for (int i = 0; i < 4; i++)
#pragma unroll
                for (int j = 0; j < 4; j++) {
                    MMA_BF16(acc[i][j], ah[i][0], ah[i][1], ah[i][2], ah[i][3],
                             bh[j][0], bh[j][1]);
                    MMA_BF16(acc[i][j], ah[i][0], ah[i][1], ah[i][2], ah[i][3],
                             bl[j][0], bl[j][1]);
                    MMA_BF16(acc[i][j], al[i][0], al[i][1], al[i][2], al[i][3],
                             bh[j][0], bh[j][1]);
                }
        }
        // ---- store next chunk into the other (idle) stage ----
        if (c < DIM/32 - 1) {
            char* st = smem + ((c + 1) & 1) * GSTAGE;
            uint32_t h[2][2], l[2][2];
            split4(ar[0], h[0], l[0]); split4(ar[1], h[1], l[1]);
            *(uint4*)(st +         soff[0]) = make_uint4(h[0][0], h[0][1], h[1][0], h[1][1]);
            *(uint4*)(st +  8192 + soff[0]) = make_uint4(l[0][0], l[0][1], l[1][0], l[1][1]);
            split4(ar[2], h[0], l[0]); split4(ar[3], h[1], l[1]);
            *(uint4*)(st +         soff[1]) = make_uint4(h[0][0], h[0][1], h[1][0], h[1][1]);
            *(uint4*)(st +  8192 + soff[1]) = make_uint4(l[0][0], l[0][1], l[1][0], l[1][1]);
            split4(br[0], h[0], l[0]); split4(br[1], h[1], l[1]);
            *(uint4*)(st + 16384 + soff[0]) = make_uint4(h[0][0], h[0][1], h[1][0], h[1][1]);
            *(uint4*)(st + 24576 + soff[0]) = make_uint4(l[0][0], l[0][1], l[1][0], l[1][1]);
            split4(br[2], h[0], l[0]); split4(br[3], h[1], l[1]);
            *(uint4*)(st + 16384 + soff[1]) = make_uint4(h[0][0], h[0][1], h[1][0], h[1][1]);
            *(uint4*)(st + 24576 + soff[1]) = make_uint4(l[0][0], l[0][1], l[1][0], l[1][1]);
        }
        __syncthreads();
    }

    // ---- epilogue: C frags -> global, bias fused ----
#pragma unroll
    for (int i = 0; i < 4; i++) {
        int r = m0 + wm*64 + i*16 + g;
#pragma unroll
        for (int j = 0; j < 4; j++) {
            int n = n0 + wn*32 + j*8 + 2*tig;
            float b0 = __ldg(bias + n), b1 = __ldg(bias + n + 1);
#pragma unroll
            for (int half = 0; half < 2; half++) {
                int m = r + half*8;
                float v0 = acc[i][j][half*2] + b0;
                float v1 = acc[i][j][half*2+1] + b1;
                if (SCATTER) {
                    // round q/k/v to tf32 so attention MMA truncation is exact
                    float2 o = make_float2(__uint_as_float(f2tf32(v0)),
                                           __uint_as_float(f2tf32(v1)));
                    int b_ = m >> 11, s_ = m & (SEQ - 1);
                    int head = n >> 6, hd = n & 63;
                    *(float2*)&C[(((size_t)(b_*NH + head)) * SEQ + s_) * HD + hd] = o;
                } else {
                    *(float2*)&C[(size_t)m * DIM + n] = make_float2(v0, v1);
                }
            }
        }
    }
}

// ===========================================================================
// Tensor-core flash attention (tf32 mma.sync) — unchanged from R4 (proven).
// ===========================================================================
#define ATTN_STAGE_F  (68*64 + 72*64)          // 8960 floats per stage
#define ATTN_SMEM     ((2*ATTN_STAGE_F + 68*64) * 4)   // 89088 bytes

__global__ __launch_bounds__(128, 2)
void attn_mma(const float* __restrict__ q, const float* __restrict__ k,
              const float* __restrict__ v, float* __restrict__ ctx)
{
    extern __shared__ float sm[];
    const uint32_t sb = smem_u32(sm);
    const int tid = threadIdx.x;
    const int lane = tid & 31, wm = tid >> 5;
    const int g = lane >> 2, tig = lane & 3;
    const int b = blockIdx.z, h = blockIdx.y, q0 = blockIdx.x * 64;

    const float* qg = q + (((size_t)(b*NH + h)) * SEQ + q0) * HD;
    const float* kg = k + ((size_t)(b*NH + h)) * SEQ * HD;
    const float* vg = v + ((size_t)(b*NH + h)) * SEQ * HD;

    float* Pbuf = sm + 2*ATTN_STAGE_F;

#pragma unroll
    for (int j = 0; j < 8; j++) {
        int id = tid + 128*j;
        int r = id >> 4, c = (id & 15) * 4;
        float4 t = *(const float4*)(qg + r*HD + c);
        t.x *= 0.125f; t.y *= 0.125f; t.z *= 0.125f; t.w *= 0.125f;
        *(float4*)&Pbuf[r*68 + c] = t;
    }
    __syncthreads();
    uint32_t qf[8][4];
    {
        int r0 = wm*16 + g;
#pragma unroll
        for (int kc = 0; kc < 8; kc++) {
            qf[kc][0] = __float_as_uint(Pbuf[ r0      *68 + kc*8 + tig    ]);
            qf[kc][1] = __float_as_uint(Pbuf[(r0 + 8) *68 + kc*8 + tig    ]);
            qf[kc][2] = __float_as_uint(Pbuf[ r0      *68 + kc*8 + tig + 4]);
            qf[kc][3] = __float_as_uint(Pbuf[(r0 + 8) *68 + kc*8 + tig + 4]);
        }
    }

#pragma unroll
    for (int j = 0; j < 8; j++) {
        int id = tid + 128*j;
        int r = id >> 4, c = (id & 15) * 4;
        cp16(sb + (r*68 + c)*4,        kg + r*HD + c);
        cp16(sb + (4352 + r*72 + c)*4, vg + r*HD + c);
    }
    CP_COMMIT();

    float o[8][4];
#pragma unroll
    for (int nc = 0; nc < 8; nc++)
#pragma unroll
        for (int e = 0; e < 4; e++) o[nc][e] = 0.f;
    float m0 = -1e30f, m1 = -1e30f, l0 = 0.f, l1 = 0.f;
    const int r0 = wm*16 + g;

    for (int t = 0; t < SEQ/64; ++t) {
        CP_WAIT0();
        __syncthreads();
        if (t < SEQ/64 - 1) {
            int st = ((t+1) & 1) * ATTN_STAGE_F;
            const float* kn = kg + (size_t)(t+1)*64*HD;
            const float* vn = vg + (size_t)(t+1)*64*HD;
#pragma unroll
            for (int j = 0; j < 8; j++) {
                int id = tid + 128*j;
                int r = id >> 4, c = (id & 15) * 4;
                cp16(sb + (st + r*68 + c)*4,        kn + r*HD + c);
                cp16(sb + (st + 4352 + r*72 + c)*4, vn + r*HD + c);
            }
            CP_COMMIT();
        }
        const float* Ks = sm + (t & 1) * ATTN_STAGE_F;
        const float* Vs = Ks + 4352;

        float s[8][4];
#pragma unroll
        for (int nc = 0; nc < 8; nc++) {
#pragma unroll
            for (int e = 0; e < 4; e++) s[nc][e] = 0.f;
#pragma unroll
            for (int kc = 0; kc < 8; kc++) {
                uint32_t bfr[2];
                bfr[0] = __float_as_uint(Ks[(nc*8 + g)*68 + kc*8 + tig    ]);
                bfr[1] = __float_as_uint(Ks[(nc*8 + g)*68 + kc*8 + tig + 4]);
                MMA_TF32(s[nc], qf[kc], bfr);
            }
        }

        float mx0 = -1e30f, mx1 = -1e30f;
#pragma unroll
        for (int nc = 0; nc < 8; nc++) {
            mx0 = fmaxf(mx0, fmaxf(s[nc][0], s[nc][1]));
            mx1 = fmaxf(mx1, fmaxf(s[nc][2], s[nc][3]));
        }
        mx0 = fmaxf(mx0, __shfl_xor_sync(0xffffffffu, mx0, 1));
        mx0 = fmaxf(mx0, __shfl_xor_sync(0xffffffffu, mx0, 2));
        mx1 = fmaxf(mx1, __shfl_xor_sync(0xffffffffu, mx1, 1));
        mx1 = fmaxf(mx1, __shfl_xor_sync(0xffffffffu, mx1, 2));
        float mn0 = fmaxf(m0, mx0), mn1 = fmaxf(m1, mx1);
        float c0 = __expf(m0 - mn0), c1 = __expf(m1 - mn1);
        float sum0 = 0.f, sum1 = 0.f;
#pragma unroll
        for (int nc = 0; nc < 8; nc++) {
            s[nc][0] = __expf(s[nc][0] - mn0); sum0 += s[nc][0];
            s[nc][1] = __expf(s[nc][1] - mn0); sum0 += s[nc][1];
            s[nc][2] = __expf(s[nc][2] - mn1); sum1 += s[nc][2];
            s[nc][3] = __expf(s[nc][3] - mn1); sum1 += s[nc][3];
        }
        sum0 += __shfl_xor_sync(0xffffffffu, sum0, 1);
        sum0 += __shfl_xor_sync(0xffffffffu, sum0, 2);
        sum1 += __shfl_xor_sync(0xffffffffu, sum1, 1);
        sum1 += __shfl_xor_sync(0xffffffffu, sum1, 2);
        l0 = l0*c0 + sum0;  l1 = l1*c1 + sum1;
        m0 = mn0;           m1 = mn1;
#pragma unroll
        for (int nc = 0; nc < 8; nc++) {
            o[nc][0] *= c0; o[nc][1] *= c0;
            o[nc][2] *= c1; o[nc][3] *= c1;
        }

#pragma unroll
        for (int nc = 0; nc < 8; nc++) {
            *(float2*)&Pbuf[ r0    *68 + nc*8 + 2*tig] =
                make_float2(__uint_as_float(f2tf32(s[nc][0])),
                            __uint_as_float(f2tf32(s[nc][1])));
            *(float2*)&Pbuf[(r0+8) *68 + nc*8 + 2*tig] =
                make_float2(__uint_as_float(f2tf32(s[nc][2])),
                            __uint_as_float(f2tf32(s[nc][3])));
        }
        __syncwarp();

#pragma unroll
        for (int kc = 0; kc < 8; kc++) {
            uint32_t a[4];
            a[0] = __float_as_uint(Pbuf[ r0    *68 + kc*8 + tig    ]);
            a[1] = __float_as_uint(Pbuf[(r0+8) *68 + kc*8 + tig    ]);
            a[2] = __float_as_uint(Pbuf[ r0    *68 + kc*8 + tig + 4]);
            a[3] = __float_as_uint(Pbuf[(r0+8) *68 + kc*8 + tig + 4]);
#pragma unroll
            for (int nc = 0; nc < 8; nc++) {
                uint32_t bfr[2];
                bfr[0] = __float_as_uint(Vs[(kc*8 + tig    )*72 + nc*8 + g]);
                bfr[1] = __float_as_uint(Vs[(kc*8 + tig + 4)*72 + nc*8 + g]);
                MMA_TF32(o[nc], a, bfr);
            }
        }
        __syncwarp();
    }

    float inv0 = 1.f / l0, inv1 = 1.f / l1;
    size_t base0 = ((size_t)(b*SEQ + q0 + r0    )) * DIM + h*HD;
    size_t base1 = ((size_t)(b*SEQ + q0 + r0 + 8)) * DIM + h*HD;
#pragma unroll
    for (int nc = 0; nc < 8; nc++) {
        *(float2*)&ctx[base0 + nc*8 + 2*tig] =
            make_float2(o[nc][0]*inv0, o[nc][1]*inv0);
        *(float2*)&ctx[base1 + nc*8 + 2*tig] =
            make_float2(o[nc][2]*inv1, o[nc][3]*inv1);
    }
}

// ===========================================================================
extern "C" void kernel_launch(void* const* d_in, const int* in_sizes, int n_in,
                              void* d_out, int out_size)
{
    const float* x  = (const float*)d_in[0];
    const float* wq = (const float*)d_in[1];
    const float* bq = (const float*)d_in[2];
    const float* wk = (const float*)d_in[3];
    const float* bk = (const float*)d_in[4];
    const float* wv = (const float*)d_in[5];
    const float* bv = (const float*)d_in[6];
    const float* wo = (const float*)d_in[7];
    const float* bo = (const float*)d_in[8];

    float *qp, *kp, *vp, *cp;
    cudaGetSymbolAddress((void**)&qp, g_q);
    cudaGetSymbolAddress((void**)&kp, g_k);
    cudaGetSymbolAddress((void**)&vp, g_v);
    cudaGetSymbolAddress((void**)&cp, g_ctx);

    cudaFuncSetAttribute(attn_mma,
                         cudaFuncAttributeMaxDynamicSharedMemorySize, ATTN_SMEM);
    cudaFuncSetAttribute(gemm_bf16<true>,
                         cudaFuncAttributeMaxDynamicSharedMemorySize, GEMM_SMEM_BYTES);
    cudaFuncSetAttribute(gemm_bf16<false>,
                         cudaFuncAttributeMaxDynamicSharedMemorySize, GEMM_SMEM_BYTES);

    float* out = (float*)d_out;
    // fused Q/K/V projections (z selects weight/bias/dst)
    gemm_bf16<true><<<dim3(DIM/128, MT/128, 3), 256, GEMM_SMEM_BYTES>>>(
        x, wq, wk, wv, bq, bk, bv, qp, kp, vp);
    attn_mma<<<dim3(SEQ/64, NH, BB), 128, ATTN_SMEM>>>(qp, kp, vp, cp);
    gemm_bf16<false><<<dim3(DIM/128, MT/128, 1), 256, GEMM_SMEM_BYTES>>>(
        cp, wo, wo, wo, bo, bo, bo, out, out, out);
}

// round 6
// speedup vs baseline: 3.1733x; 1.1881x over previous
#include <cuda_runtime.h>
#include <cuda_bf16.h>
#include <cstdint>
#include <math.h>

#define BB   2
#define SEQ  2048
#define DIM  1024
#define NH   16
#define HD   64
#define MT   (BB*SEQ)   // 4096

// Scratch (allocation-free rule: __device__ globals)
__device__ float g_q[BB*NH*SEQ*HD];
__device__ float g_k[BB*NH*SEQ*HD];
__device__ float g_v[BB*NH*SEQ*HD];
__device__ uint32_t g_xh[MT*DIM/2],    g_xl[MT*DIM/2];      // x split (bf16x2)
__device__ uint32_t g_wh[4*DIM*DIM/2], g_wl[4*DIM*DIM/2];   // wq|wk|wv|wo split
__device__ uint32_t g_ch[MT*DIM/2],    g_cl[MT*DIM/2];      // ctx split

// ---------------------------------------------------------------------------
// helpers
// ---------------------------------------------------------------------------
__device__ __forceinline__ uint32_t f2tf32(float x) {
    uint32_t r;
    asm("cvt.rna.tf32.f32 %0, %1;" : "=r"(r) : "f"(x));
    return r;
}
__device__ __forceinline__ uint32_t smem_u32(const void* p) {
    uint32_t a;
    asm("{ .reg .u64 t; cvta.to.shared.u64 t, %1; cvt.u32.u64 %0, t; }"
        : "=r"(a) : "l"(p));
    return a;
}
__device__ __forceinline__ void cp16(uint32_t dst, const void* src) {
    asm volatile("cp.async.ca.shared.global [%0], [%1], 16;" :: "r"(dst), "l"(src));
}
#define CP_COMMIT() asm volatile("cp.async.commit_group;" ::: "memory")
#define CP_WAIT0()  asm volatile("cp.async.wait_group 0;" ::: "memory")
#define CP_WAIT1()  asm volatile("cp.async.wait_group 1;" ::: "memory")

#define MMA_TF32(d, a, b) \
    asm volatile("mma.sync.aligned.m16n8k8.row.col.f32.tf32.tf32.f32 " \
        "{%0,%1,%2,%3}, {%4,%5,%6,%7}, {%8,%9}, {%0,%1,%2,%3};" \
        : "+f"((d)[0]), "+f"((d)[1]), "+f"((d)[2]), "+f"((d)[3]) \
        : "r"((a)[0]), "r"((a)[1]), "r"((a)[2]), "r"((a)[3]), \
          "r"((b)[0]), "r"((b)[1]))

#define MMA_BF16(d, a0, a1, a2, a3, b0, b1) \
    asm volatile("mma.sync.aligned.m16n8k16.row.col.f32.bf16.bf16.f32 " \
        "{%0,%1,%2,%3}, {%4,%5,%6,%7}, {%8,%9}, {%0,%1,%2,%3};" \
        : "+f"((d)[0]), "+f"((d)[1]), "+f"((d)[2]), "+f"((d)[3]) \
        : "r"(a0), "r"(a1), "r"(a2), "r"(a3), "r"(b0), "r"(b1))

#define LDSM4(d0, d1, d2, d3, a) \
    asm volatile("ldmatrix.sync.aligned.m8n8.x4.shared.b16 {%0,%1,%2,%3}, [%4];" \
        : "=r"(d0), "=r"(d1), "=r"(d2), "=r"(d3) : "r"(a))

// word = { low half = bf16(e0), high half = bf16(e1) }
__device__ __forceinline__ uint32_t packbf(float e0, float e1) {
    uint32_t r;
    asm("cvt.rn.bf16x2.f32 %0, %1, %2;" : "=r"(r) : "f"(e1), "f"(e0));
    return r;
}
__device__ __forceinline__ float ubf_lo(uint32_t w) { return __uint_as_float(w << 16); }
__device__ __forceinline__ float ubf_hi(uint32_t w) { return __uint_as_float(w & 0xFFFF0000u); }

// ===========================================================================
// split: fp32 -> bf16 hi + bf16 lo (lo = rn(x - hi)), 8 elements / thread
// ===========================================================================
__global__ __launch_bounds__(256)
void split_k(const float* __restrict__ src, uint32_t* __restrict__ hi,
             uint32_t* __restrict__ lo, int n8)
{
    int i = blockIdx.x * 256 + threadIdx.x;
    if (i >= n8) return;
    const float4* s = (const float4*)src;
    float4 a = s[2*i], b = s[2*i+1];
    uint32_t h0 = packbf(a.x, a.y), h1 = packbf(a.z, a.w);
    uint32_t h2 = packbf(b.x, b.y), h3 = packbf(b.z, b.w);
    uint4 H = make_uint4(h0, h1, h2, h3);
    uint4 L = make_uint4(
        packbf(a.x - ubf_lo(h0), a.y - ubf_hi(h0)),
        packbf(a.z - ubf_lo(h1), a.w - ubf_hi(h1)),
        packbf(b.x - ubf_lo(h2), b.y - ubf_hi(h2)),
        packbf(b.z - ubf_lo(h3), b.w - ubf_hi(h3)));
    ((uint4*)hi)[i] = H;
    ((uint4*)lo)[i] = L;
}

// ===========================================================================
// 3xBF16 GEMM v2: C[M,N] = A[M,K] @ W[N,K]^T + bias, pre-split bf16 inputs.
// CTA 128x128, 128 threads (4 warps, 2m x 2n, warp tile 64x64), BK=32.
// cp.async double buffer; stage = Ah|Al|Bh|Bl, each 8KB, line-interleaved
// swizzle (2 rows / 128B line, 16B chunks XOR line&7). 2 CTAs / SM.
// grid.z selects W-region/bias/C. SCATTER writes [B,H,S,HD] + tf32 round.
// ===========================================================================
#define GSTAGE2 32768
#define GEMM2_SMEM (2*GSTAGE2)   // 64 KB

template<bool SCATTER>
__global__ __launch_bounds__(128, 2)
void gemm_v2(const __nv_bfloat16* __restrict__ Ah, const __nv_bfloat16* __restrict__ Al,
             const __nv_bfloat16* __restrict__ Whb, const __nv_bfloat16* __restrict__ Wlb,
             const float* __restrict__ b0_, const float* __restrict__ b1_,
             const float* __restrict__ b2_,
             float* __restrict__ c0_, float* __restrict__ c1_, float* __restrict__ c2_)
{
    extern __shared__ char smem[];
    const uint32_t sb = smem_u32(smem);
    const int z = blockIdx.z;
    const __nv_bfloat16* Wh = Whb + (size_t)z * (DIM*DIM);
    const __nv_bfloat16* Wl = Wlb + (size_t)z * (DIM*DIM);
    const float* bias = (z == 0) ? b0_ : (z == 1) ? b1_ : b2_;
    float* C          = (z == 0) ? c0_ : (z == 1) ? c1_ : c2_;

    const int tid = threadIdx.x, lane = tid & 31, wid = tid >> 5;
    const int g = lane >> 2, tig = lane & 3;
    const int wm = wid & 1, wn = wid >> 1;          // 2m x 2n warp grid
    const int m0 = blockIdx.y * 128, n0 = blockIdx.x * 128;

    // cp.async maps: comp {Ah,Al,Wh,Wl}; rep 0..3: id=tid+128*rep -> row=id>>2, c16=id&3
    const char* gsrc[4];
    gsrc[0] = (const char*)(Ah + (size_t)m0 * DIM);
    gsrc[1] = (const char*)(Al + (size_t)m0 * DIM);
    gsrc[2] = (const char*)(Wh + (size_t)n0 * DIM);
    gsrc[3] = (const char*)(Wl + (size_t)n0 * DIM);
    uint32_t sOff[4], gOff[4];
#pragma unroll
    for (int rep = 0; rep < 4; rep++) {
        int id = tid + 128*rep;
        int row = id >> 2, cc = id & 3;
        sOff[rep] = (uint32_t)((row >> 1)*128 + ((((row & 1)*4 + cc) ^ ((row >> 1) & 7)) * 16));
        gOff[rep] = (uint32_t)((row * DIM + cc*8) * 2);
    }

    // ldmatrix per-lane offsets (kk = 0,1)
    const int rl  = ((lane >> 3) & 1) * 8 + (lane & 7);
    const int chl = lane >> 4;
    uint32_t aoff[2];
#pragma unroll
    for (int kk = 0; kk < 2; kk++)
        aoff[kk] = (uint32_t)((rl >> 1)*128 + ((((rl & 1)*4 + 2*kk + chl) ^ ((rl >> 1) & 7)) * 16));

    float acc[4][8][4];
#pragma unroll
    for (int i = 0; i < 4; i++)
#pragma unroll
        for (int j = 0; j < 8; j++)
#pragma unroll
            for (int q = 0; q < 4; q++) acc[i][j][q] = 0.f;

    // issue chunk loads
    auto issue = [&](int chunk) {
        uint32_t st = sb + (uint32_t)(chunk & 1) * GSTAGE2;
        uint32_t kb = (uint32_t)(chunk * 32 * 2);
#pragma unroll
        for (int rep = 0; rep < 4; rep++)
#pragma unroll
            for (int comp = 0; comp < 4; comp++)
                cp16(st + comp*8192u + sOff[rep], gsrc[comp] + gOff[rep] + kb);
        CP_COMMIT();
    };

    issue(0);
    for (int c = 0; c < DIM/32; ++c) {
        if (c < DIM/32 - 1) { issue(c + 1); CP_WAIT1(); }
        else                { CP_WAIT0(); }
        __syncthreads();

        const uint32_t stage = sb + (uint32_t)(c & 1) * GSTAGE2;
#pragma unroll
        for (int kk = 0; kk < 2; kk++) {
            uint32_t ah[4][4], al[4][4];
#pragma unroll
            for (int i = 0; i < 4; i++) {
                uint32_t base = stage + (uint32_t)(wm*4096 + i*1024) + aoff[kk];
                LDSM4(ah[i][0], ah[i][1], ah[i][2], ah[i][3], base);
                LDSM4(al[i][0], al[i][1], al[i][2], al[i][3], base + 8192u);
            }
#pragma unroll
            for (int nn = 0; nn < 4; nn++) {
                uint32_t base = stage + 16384u + (uint32_t)(wn*4096 + nn*1024) + aoff[kk];
                uint32_t q0, q1, q2, q3, r0_, r1_, r2_, r3_;
                LDSM4(q0, q1, q2, q3, base);
                LDSM4(r0_, r1_, r2_, r3_, base + 8192u);
                const int j0 = nn*2, j1 = nn*2 + 1;
#pragma unroll
                for (int i = 0; i < 4; i++) {
                    MMA_BF16(acc[i][j0], ah[i][0], ah[i][1], ah[i][2], ah[i][3], q0, q2);
                    MMA_BF16(acc[i][j0], ah[i][0], ah[i][1], ah[i][2], ah[i][3], r0_, r2_);
                    MMA_BF16(acc[i][j0], al[i][0], al[i][1], al[i][2], al[i][3], q0, q2);
                    MMA_BF16(acc[i][j1], ah[i][0], ah[i][1], ah[i][2], ah[i][3], q1, q3);
                    MMA_BF16(acc[i][j1], ah[i][0], ah[i][1], ah[i][2], ah[i][3], r1_, r3_);
                    MMA_BF16(acc[i][j1], al[i][0], al[i][1], al[i][2], al[i][3], q1, q3);
                }
            }
        }
        __syncthreads();   // all warps done with this stage before rewrite
    }

    // epilogue
#pragma unroll
    for (int i = 0; i < 4; i++) {
        int r = m0 + wm*64 + i*16 + g;
#pragma unroll
        for (int j = 0; j < 8; j++) {
            int n = n0 + wn*64 + j*8 + 2*tig;
            float b0 = __ldg(bias + n), b1 = __ldg(bias + n + 1);
#pragma unroll
            for (int half = 0; half < 2; half++) {
                int m = r + half*8;
                float v0 = acc[i][j][half*2] + b0;
                float v1 = acc[i][j][half*2+1] + b1;
                if (SCATTER) {
                    float2 o = make_float2(__uint_as_float(f2tf32(v0)),
                                           __uint_as_float(f2tf32(v1)));
                    int b_ = m >> 11, s_ = m & (SEQ - 1);
                    int head = n >> 6, hd = n & 63;
                    *(float2*)&C[(((size_t)(b_*NH + head)) * SEQ + s_) * HD + hd] = o;
                } else {
                    *(float2*)&C[(size_t)m * DIM + n] = make_float2(v0, v1);
                }
            }
        }
    }
}

// ===========================================================================
// Tensor-core flash attention (tf32) — R4/R5 core; epilogue now writes ctx
// directly as bf16 hi/lo (consumed by the out-projection GEMM).
// ===========================================================================
#define ATTN_STAGE_F  (68*64 + 72*64)
#define ATTN_SMEM     ((2*ATTN_STAGE_F + 68*64) * 4)

__global__ __launch_bounds__(128, 2)
void attn_mma(const float* __restrict__ q, const float* __restrict__ k,
              const float* __restrict__ v,
              uint32_t* __restrict__ ch, uint32_t* __restrict__ cl)
{
    extern __shared__ float sm[];
    const uint32_t sb = smem_u32(sm);
    const int tid = threadIdx.x;
    const int lane = tid & 31, wm = tid >> 5;
    const int g = lane >> 2, tig = lane & 3;
    const int b = blockIdx.z, h = blockIdx.y, q0 = blockIdx.x * 64;

    const float* qg = q + (((size_t)(b*NH + h)) * SEQ + q0) * HD;
    const float* kg = k + ((size_t)(b*NH + h)) * SEQ * HD;
    const float* vg = v + ((size_t)(b*NH + h)) * SEQ * HD;

    float* Pbuf = sm + 2*ATTN_STAGE_F;

#pragma unroll
    for (int j = 0; j < 8; j++) {
        int id = tid + 128*j;
        int r = id >> 4, c = (id & 15) * 4;
        float4 t = *(const float4*)(qg + r*HD + c);
        t.x *= 0.125f; t.y *= 0.125f; t.z *= 0.125f; t.w *= 0.125f;
        *(float4*)&Pbuf[r*68 + c] = t;
    }
    __syncthreads();
    uint32_t qf[8][4];
    {
        int r0 = wm*16 + g;
#pragma unroll
        for (int kc = 0; kc < 8; kc++) {
            qf[kc][0] = __float_as_uint(Pbuf[ r0      *68 + kc*8 + tig    ]);
            qf[kc][1] = __float_as_uint(Pbuf[(r0 + 8) *68 + kc*8 + tig    ]);
            qf[kc][2] = __float_as_uint(Pbuf[ r0      *68 + kc*8 + tig + 4]);
            qf[kc][3] = __float_as_uint(Pbuf[(r0 + 8) *68 + kc*8 + tig + 4]);
        }
    }

#pragma unroll
    for (int j = 0; j < 8; j++) {
        int id = tid + 128*j;
        int r = id >> 4, c = (id & 15) * 4;
        cp16(sb + (r*68 + c)*4,        kg + r*HD + c);
        cp16(sb + (4352 + r*72 + c)*4, vg + r*HD + c);
    }
    CP_COMMIT();

    float o[8][4];
#pragma unroll
    for (int nc = 0; nc < 8; nc++)
#pragma unroll
        for (int e = 0; e < 4; e++) o[nc][e] = 0.f;
    float m0 = -1e30f, m1 = -1e30f, l0 = 0.f, l1 = 0.f;
    const int r0 = wm*16 + g;

    for (int t = 0; t < SEQ/64; ++t) {
        CP_WAIT0();
        __syncthreads();
        if (t < SEQ/64 - 1) {
            int st = ((t+1) & 1) * ATTN_STAGE_F;
            const float* kn = kg + (size_t)(t+1)*64*HD;
            const float* vn = vg + (size_t)(t+1)*64*HD;
#pragma unroll
            for (int j = 0; j < 8; j++) {
                int id = tid + 128*j;
                int r = id >> 4, c = (id & 15) * 4;
                cp16(sb + (st + r*68 + c)*4,        kn + r*HD + c);
                cp16(sb + (st + 4352 + r*72 + c)*4, vn + r*HD + c);
            }
            CP_COMMIT();
        }
        const float* Ks = sm + (t & 1) * ATTN_STAGE_F;
        const float* Vs = Ks + 4352;

        float s[8][4];
#pragma unroll
        for (int nc = 0; nc < 8; nc++) {
#pragma unroll
            for (int e = 0; e < 4; e++) s[nc][e] = 0.f;
#pragma unroll
            for (int kc = 0; kc < 8; kc++) {
                uint32_t bfr[2];
                bfr[0] = __float_as_uint(Ks[(nc*8 + g)*68 + kc*8 + tig    ]);
                bfr[1] = __float_as_uint(Ks[(nc*8 + g)*68 + kc*8 + tig + 4]);
                MMA_TF32(s[nc], qf[kc], bfr);
            }
        }

        float mx0 = -1e30f, mx1 = -1e30f;
#pragma unroll
        for (int nc = 0; nc < 8; nc++) {
            mx0 = fmaxf(mx0, fmaxf(s[nc][0], s[nc][1]));
            mx1 = fmaxf(mx1, fmaxf(s[nc][2], s[nc][3]));
        }
        mx0 = fmaxf(mx0, __shfl_xor_sync(0xffffffffu, mx0, 1));
        mx0 = fmaxf(mx0, __shfl_xor_sync(0xffffffffu, mx0, 2));
        mx1 = fmaxf(mx1, __shfl_xor_sync(0xffffffffu, mx1, 1));
        mx1 = fmaxf(mx1, __shfl_xor_sync(0xffffffffu, mx1, 2));
        float mn0 = fmaxf(m0, mx0), mn1 = fmaxf(m1, mx1);
        float c0 = __expf(m0 - mn0), c1 = __expf(m1 - mn1);
        float sum0 = 0.f, sum1 = 0.f;
#pragma unroll
        for (int nc = 0; nc < 8; nc++) {
            s[nc][0] = __expf(s[nc][0] - mn0); sum0 += s[nc][0];
            s[nc][1] = __expf(s[nc][1] - mn0); sum0 += s[nc][1];
            s[nc][2] = __expf(s[nc][2] - mn1); sum1 += s[nc][2];
            s[nc][3] = __expf(s[nc][3] - mn1); sum1 += s[nc][3];
        }
        sum0 += __shfl_xor_sync(0xffffffffu, sum0, 1);
        sum0 += __shfl_xor_sync(0xffffffffu, sum0, 2);
        sum1 += __shfl_xor_sync(0xffffffffu, sum1, 1);
        sum1 += __shfl_xor_sync(0xffffffffu, sum1, 2);
        l0 = l0*c0 + sum0;  l1 = l1*c1 + sum1;
        m0 = mn0;           m1 = mn1;
#pragma unroll
        for (int nc = 0; nc < 8; nc++) {
            o[nc][0] *= c0; o[nc][1] *= c0;
            o[nc][2] *= c1; o[nc][3] *= c1;
        }

#pragma unroll
        for (int nc = 0; nc < 8; nc++) {
            *(float2*)&Pbuf[ r0    *68 + nc*8 + 2*tig] =
                make_float2(__uint_as_float(f2tf32(s[nc][0])),
                            __uint_as_float(f2tf32(s[nc][1])));
            *(float2*)&Pbuf[(r0+8) *68 + nc*8 + 2*tig] =
                make_float2(__uint_as_float(f2tf32(s[nc][2])),
                            __uint_as_float(f2tf32(s[nc][3])));
        }
        __syncwarp();

#pragma unroll
        for (int kc = 0; kc < 8; kc++) {
            uint32_t a[4];
            a[0] = __float_as_uint(Pbuf[ r0    *68 + kc*8 + tig    ]);
            a[1] = __float_as_uint(Pbuf[(r0+8) *68 + kc*8 + tig    ]);
            a[2] = __float_as_uint(Pbuf[ r0    *68 + kc*8 + tig + 4]);
            a[3] = __float_as_uint(Pbuf[(r0+8) *68 + kc*8 + tig + 4]);
#pragma unroll
            for (int nc = 0; nc < 8; nc++) {
                uint32_t bfr[2];
                bfr[0] = __float_as_uint(Vs[(kc*8 + tig    )*72 + nc*8 + g]);
                bfr[1] = __float_as_uint(Vs[(kc*8 + tig + 4)*72 + nc*8 + g]);
                MMA_TF32(o[nc], a, bfr);
            }
        }
        __syncwarp();
    }

    // epilogue: write ctx as bf16 hi/lo pairs
    float inv0 = 1.f / l0, inv1 = 1.f / l1;
    size_t base0 = ((size_t)(b*SEQ + q0 + r0    )) * DIM + h*HD;
    size_t base1 = ((size_t)(b*SEQ + q0 + r0 + 8)) * DIM + h*HD;
#pragma unroll
    for (int nc = 0; nc < 8; nc++) {
        float v0 = o[nc][0]*inv0, v1 = o[nc][1]*inv0;
        uint32_t hw = packbf(v0, v1);
        uint32_t lw = packbf(v0 - ubf_lo(hw), v1 - ubf_hi(hw));
        size_t idx = (base0 + nc*8 + 2*tig) >> 1;
        ch[idx] = hw; cl[idx] = lw;
        v0 = o[nc][2]*inv1; v1 = o[nc][3]*inv1;
        hw = packbf(v0, v1);
        lw = packbf(v0 - ubf_lo(hw), v1 - ubf_hi(hw));
        idx = (base1 + nc*8 + 2*tig) >> 1;
        ch[idx] = hw; cl[idx] = lw;
    }
}

// ===========================================================================
extern "C" void kernel_launch(void* const* d_in, const int* in_sizes, int n_in,
                              void* d_out, int out_size)
{
    const float* x  = (const float*)d_in[0];
    const float* wq = (const float*)d_in[1];
    const float* bq = (const float*)d_in[2];
    const float* wk = (const float*)d_in[3];
    const float* bk = (const float*)d_in[4];
    const float* wv = (const float*)d_in[5];
    const float* bv = (const float*)d_in[6];
    const float* wo = (const float*)d_in[7];
    const float* bo = (const float*)d_in[8];

    float *qp, *kp, *vp;
    uint32_t *xh, *xl, *wh, *wl, *ch, *cl;
    cudaGetSymbolAddress((void**)&qp, g_q);
    cudaGetSymbolAddress((void**)&kp, g_k);
    cudaGetSymbolAddress((void**)&vp, g_v);
    cudaGetSymbolAddress((void**)&xh, g_xh);
    cudaGetSymbolAddress((void**)&xl, g_xl);
    cudaGetSymbolAddress((void**)&wh, g_wh);
    cudaGetSymbolAddress((void**)&wl, g_wl);
    cudaGetSymbolAddress((void**)&ch, g_ch);
    cudaGetSymbolAddress((void**)&cl, g_cl);

    cudaFuncSetAttribute(attn_mma,
                         cudaFuncAttributeMaxDynamicSharedMemorySize, ATTN_SMEM);
    cudaFuncSetAttribute(gemm_v2<true>,
                         cudaFuncAttributeMaxDynamicSharedMemorySize, GEMM2_SMEM);
    cudaFuncSetAttribute(gemm_v2<false>,
                         cudaFuncAttributeMaxDynamicSharedMemorySize, GEMM2_SMEM);

    // 1) split x and weights to bf16 hi/lo
    const int WE = DIM*DIM;                 // 1M elements per weight
    split_k<<<MT*DIM/8/256, 256>>>(x,  xh, xl, MT*DIM/8);
    split_k<<<WE/8/256, 256>>>(wq, wh,              wl,              WE/8);
    split_k<<<WE/8/256, 256>>>(wk, wh + WE/2,       wl + WE/2,       WE/8);
    split_k<<<WE/8/256, 256>>>(wv, wh + 2*(WE/2),   wl + 2*(WE/2),   WE/8);
    split_k<<<WE/8/256, 256>>>(wo, wh + 3*(WE/2),   wl + 3*(WE/2),   WE/8);

    const __nv_bfloat16* xh_b = (const __nv_bfloat16*)xh;
    const __nv_bfloat16* xl_b = (const __nv_bfloat16*)xl;
    const __nv_bfloat16* wh_b = (const __nv_bfloat16*)wh;
    const __nv_bfloat16* wl_b = (const __nv_bfloat16*)wl;
    const __nv_bfloat16* ch_b = (const __nv_bfloat16*)ch;
    const __nv_bfloat16* cl_b = (const __nv_bfloat16*)cl;
    float* out = (float*)d_out;

    // 2) fused QKV projections
    gemm_v2<true><<<dim3(DIM/128, MT/128, 3), 128, GEMM2_SMEM>>>(
        xh_b, xl_b, wh_b, wl_b, bq, bk, bv, qp, kp, vp);
    // 3) attention (writes ctx hi/lo)
    attn_mma<<<dim3(SEQ/64, NH, BB), 128, ATTN_SMEM>>>(qp, kp, vp, ch, cl);
    // 4) output projection
    gemm_v2<false><<<dim3(DIM/128, MT/128, 1), 128, GEMM2_SMEM>>>(
        ch_b, cl_b, wh_b + (size_t)3*WE, wl_b + (size_t)3*WE,
        bo, bo, bo, out, out, out);
}